// round 13
// baseline (speedup 1.0000x reference)
#include <cuda_runtime.h>

#define BB 4
#define N1 2048
#define N2 8192
#define CIN 64
#define COUT 128
#define NKP 15
#define NS 32
#define RADIUS2 0.01f
#define INV_EXTENT 25.0f   /* 1 / 0.04 */
#define GRID 10
#define NCELL (GRID * GRID * GRID)
#define NCAND 128
#define NBIN 8             /* binning blocks per batch, 125 cells each */

// ---------------- scratch (__device__ globals: allocation-free rule) --------
__device__ __align__(16) float  g_featT[BB * N2 * CIN];  // 8 MB [B][N2][C]
__device__ __align__(16) float  g_tmp1[BB * N1 * CIN];   // 2 MB [B][N1][C]
__device__ float4 g_binned[BB * N2];             // points grouped by cell
__device__ int    g_cellStart[BB * (NCELL + 1)]; // cumulative starts per batch
__device__ float  g_sum[COUT];
__device__ float  g_sumsq[COUT];

// ---------------- f32x2 helpers (FFMA2) -------------------------------------
__device__ __forceinline__ unsigned long long pack2(float a, float b) {
    unsigned long long r;
    asm("mov.b64 %0, {%1, %2};" : "=l"(r) : "f"(a), "f"(b));
    return r;
}
__device__ __forceinline__ unsigned long long fma2(unsigned long long a,
                                                   unsigned long long b,
                                                   unsigned long long c) {
    unsigned long long d;
    asm("fma.rn.f32x2 %0, %1, %2, %3;" : "=l"(d) : "l"(a), "l"(b), "l"(c));
    return d;
}

__device__ __forceinline__ int cell1d(float x) {
    int c = (int)(x * (float)GRID);
    return c < 0 ? 0 : (c > GRID - 1 ? GRID - 1 : c);
}

// generic in-warp bitonic sort of R*32 keys (R regs/lane), ascending
template <int R>
__device__ __forceinline__ void bitonic_sort(unsigned (&v)[R], int lane) {
    const unsigned FULL = 0xffffffffu;
#pragma unroll
    for (int k = 2; k <= R * 32; k <<= 1) {
#pragma unroll
        for (int d = k >> 1; d > 0; d >>= 1) {
            if (d >= 32) {
                int rd = d >> 5;
#pragma unroll
                for (int r = 0; r < R; r++) {
                    if ((r & rd) == 0) {
                        int r2 = r + rd;
                        bool asc = (((r * 32) & k) == 0);
                        unsigned a = v[r], b2 = v[r2];
                        unsigned mn = a < b2 ? a : b2;
                        unsigned mx = a < b2 ? b2 : a;
                        v[r] = asc ? mn : mx;
                        v[r2] = asc ? mx : mn;
                    }
                }
            } else {
#pragma unroll
                for (int r = 0; r < R; r++) {
                    unsigned p = __shfl_xor_sync(FULL, v[r], d);
                    int idx = r * 32 + lane;
                    bool asc = ((idx & k) == 0);
                    bool lower = ((lane & d) == 0);
                    unsigned mn = v[r] < p ? v[r] : p;
                    unsigned mx = v[r] < p ? p : v[r];
                    v[r] = (lower == asc) ? mn : mx;
                }
            }
        }
    }
}

// ---------------------------------------------------------------------------
// k_prep: blocks 0..31  -> binning: block (b,k) owns cells [125k, 125k+125)
//         blocks 32..   -> transpose [B][C][N2] -> [B][N2][C]
// ---------------------------------------------------------------------------
__global__ __launch_bounds__(1024) void k_prep(const float* __restrict__ f,
                                               const float* __restrict__ sxyz,
                                               const float* __restrict__ smask) {
    __shared__ float tile[32][260];   // 33.3 KB transpose tile
    __shared__ int s_h[128];
    __shared__ int s_before[32];
    __shared__ int s_gbase;

    int t = threadIdx.x;
    int lane = t & 31, w = t >> 5;
    const unsigned FULL = 0xffffffffu;

    if (blockIdx.x < BB * NBIN) {
        // ================= binning block (b, k) =================
        int b = blockIdx.x >> 3, k = blockIdx.x & 7;
        int base = k * 125;

        if (b == 0 && k == 0 && t < COUT) { g_sum[t] = 0.0f; g_sumsq[t] = 0.0f; }
        if (t < 128) s_h[t] = 0;
        __syncthreads();

        int myBefore = 0;
#pragma unroll
        for (int i = 0; i < 8; i++) {
            int j = i * 1024 + t, p = b * N2 + j;
            if (smask[p] > 0.0f) {
                int cid = (cell1d(sxyz[p * 3]) * GRID + cell1d(sxyz[p * 3 + 1])) * GRID +
                          cell1d(sxyz[p * 3 + 2]);
                if (cid < base) myBefore++;
                else if (cid < base + 125) atomicAdd(&s_h[cid - base], 1);
            }
        }
#pragma unroll
        for (int o = 16; o; o >>= 1) myBefore += __shfl_xor_sync(FULL, myBefore, o);
        if (lane == 0) s_before[w] = myBefore;
        __syncthreads();
        if (w == 0) {
            int sv = s_before[lane];
#pragma unroll
            for (int o = 16; o; o >>= 1) sv += __shfl_xor_sync(FULL, sv, o);
            if (lane == 0) s_gbase = sv;
        }
        __syncthreads();
        int gbase = s_gbase;
        __syncthreads();

        if (w == 0) {
            int c0 = base + 4 * lane;
            int v0 = (4 * lane + 0 < 125) ? s_h[4 * lane + 0] : 0;
            int v1 = (4 * lane + 1 < 125) ? s_h[4 * lane + 1] : 0;
            int v2 = (4 * lane + 2 < 125) ? s_h[4 * lane + 2] : 0;
            int v3 = (4 * lane + 3 < 125) ? s_h[4 * lane + 3] : 0;
            int sum = v0 + v1 + v2 + v3;
            int incl = sum;
#pragma unroll
            for (int o = 1; o < 32; o <<= 1) {
                int n = __shfl_up_sync(FULL, incl, o);
                if (lane >= o) incl += n;
            }
            int total = __shfl_sync(FULL, incl, 31);
            int e0 = incl - sum;
            int e1 = e0 + v0, e2 = e1 + v1, e3 = e2 + v2;
            int* gs = g_cellStart + b * (NCELL + 1);
            if (4 * lane + 0 < 125) { s_h[4 * lane + 0] = gbase + e0; gs[c0 + 0] = gbase + e0; }
            if (4 * lane + 1 < 125) { s_h[4 * lane + 1] = gbase + e1; gs[c0 + 1] = gbase + e1; }
            if (4 * lane + 2 < 125) { s_h[4 * lane + 2] = gbase + e2; gs[c0 + 2] = gbase + e2; }
            if (4 * lane + 3 < 125) { s_h[4 * lane + 3] = gbase + e3; gs[c0 + 3] = gbase + e3; }
            if (k == NBIN - 1 && lane == 0) gs[NCELL] = gbase + total;
        }
        __syncthreads();

#pragma unroll
        for (int i = 0; i < 8; i++) {
            int j = i * 1024 + t, p = b * N2 + j;
            if (smask[p] > 0.0f) {
                float x = sxyz[p * 3], y = sxyz[p * 3 + 1], z = sxyz[p * 3 + 2];
                int cid = (cell1d(x) * GRID + cell1d(y)) * GRID + cell1d(z);
                if (cid >= base && cid < base + 125) {
                    int pos = atomicAdd(&s_h[cid - base], 1);
                    g_binned[b * N2 + pos] = make_float4(x, y, z, __int_as_float(j));
                }
            }
        }
    } else {
        // ================= transpose tile: 32 channels x 256 points =========
        int tb = blockIdx.x - BB * NBIN;   // 0..255
        int n0 = (tb & 31) * 256;
        int c0 = ((tb >> 5) & 1) * 32;
        int b = tb >> 6;

        const float4* f4 = (const float4*)f;
#pragma unroll
        for (int i = 0; i < 2; i++) {
            int idx = t + i * 1024;
            int row = idx >> 6;
            int col4 = idx & 63;
            float4 vv = f4[(((size_t)(b * CIN + c0 + row) * N2) + n0) / 4 + col4];
            *(float4*)&tile[row][col4 * 4] = vv;
        }
        __syncthreads();
        float4* o4 = (float4*)g_featT;
#pragma unroll
        for (int i = 0; i < 2; i++) {
            int idx = t + i * 1024;
            int n = idx >> 3;
            int c4 = idx & 7;
            float4 vv = make_float4(tile[c4 * 4 + 0][n], tile[c4 * 4 + 1][n],
                                    tile[c4 * 4 + 2][n], tile[c4 * 4 + 3][n]);
            o4[((size_t)(b * N2 + n0 + n) * CIN + c0) / 4 + c4] = vv;
        }
    }
}

// ---------------------------------------------------------------------------
// k_group: grid-hashed ordered ball query + kernel-point weighting +
//          aggregation. One warp per query; 8 queries per 256-thread block.
//          Phase C weights read via LDS.128 (2 {w,w} pairs per load).
// ---------------------------------------------------------------------------
__global__ __launch_bounds__(256) void k_group(
    const float* __restrict__ qxyz, const float* __restrict__ qmask,
    const float* __restrict__ sxyz,
    const float* __restrict__ kp, const float* __restrict__ kw) {
    __shared__ float4 s_cand[8][NCAND];                         // 16 KB
    __shared__ __align__(16) unsigned long long s_w2[8][NS][16]; // 32 KB padded
    __shared__ int s_ji[8][NS];                                 // 1 KB

    int b = blockIdx.y;
    int warp = threadIdx.x >> 5, lane = threadIdx.x & 31;
    int q = blockIdx.x * 8 + warp;
    unsigned lmask = (1u << lane) - 1u;
    const unsigned FULL = 0xffffffffu;

    float qx = qxyz[(b * N1 + q) * 3 + 0];
    float qy = qxyz[(b * N1 + q) * 3 + 1];
    float qz = qxyz[(b * N1 + q) * 3 + 2];
    float qm = qmask[b * N1 + q];

    // ---- phase A: flattened candidate scan over 9 z-contiguous segments ----
    int cx = cell1d(qx), cy = cell1d(qy), cz = cell1d(qz);
    int z0 = cz > 0 ? cz - 1 : 0, z1 = cz < GRID - 1 ? cz + 1 : GRID - 1;

    const int* cs = g_cellStart + b * (NCELL + 1);
    int seg_s0 = 0, seg_len = 0;
    if (lane < 9) {
        int ix = cx + lane / 3 - 1;
        int iy = cy + lane % 3 - 1;
        if (ix >= 0 && ix < GRID && iy >= 0 && iy < GRID) {
            int cbase = (ix * GRID + iy) * GRID;
            seg_s0 = cs[cbase + z0];
            seg_len = cs[cbase + z1 + 1] - seg_s0;
        }
    }
    int cum = seg_len;
#pragma unroll
    for (int o = 1; o < 16; o <<= 1) {
        int n = __shfl_up_sync(FULL, cum, o);
        if (lane >= o) cum += n;
    }
    int T = __shfl_sync(FULL, cum, 8);
    int cumk[9], s0k[9];
#pragma unroll
    for (int k = 0; k < 9; k++) {
        cumk[k] = __shfl_sync(FULL, cum, k);
        s0k[k] = __shfl_sync(FULL, seg_s0, k);
    }

    int cnt = 0;
    for (int t0 = 0; t0 < T; t0 += 32) {
        int g = t0 + lane;
        bool inb = g < T;
        int addr = s0k[0] + g;
#pragma unroll
        for (int k = 1; k < 9; k++)
            if (g >= cumk[k - 1]) addr = s0k[k] + (g - cumk[k - 1]);
        if (!inb) addr = 0;
        float4 p = g_binned[b * N2 + addr];
        float rx = p.x - qx, ry = p.y - qy, rz = p.z - qz;
        float d2 = rx * rx + ry * ry + rz * rz;
        bool valid = inb && (d2 < RADIUS2);
        unsigned bal = __ballot_sync(FULL, valid);
        int slot = cnt + __popc(bal & lmask);
        if (valid && slot < NCAND)
            s_cand[warp][slot] = make_float4(rx, ry, rz, p.w);
        cnt += __popc(bal);
    }
    __syncwarp();

    // ---- phase B: first-32 SET selection + kernel-point weights ----
    int cap = cnt < NS ? cnt : NS;
    float4 nb;
    int j;
    float fm;

    if (cnt == 0) {
        nb = make_float4(sxyz[b * N2 * 3] - qx, sxyz[b * N2 * 3 + 1] - qy,
                         sxyz[b * N2 * 3 + 2] - qz, 0.0f);
        j = 0;
        fm = 1.0f - qm;
    } else if (cnt <= NS) {
        unsigned mykey = 0xFFFFFFFFu;
        float4 myc;
        if (lane < cap) {
            myc = s_cand[warp][lane];
            mykey = ((unsigned)__float_as_int(myc.w) << 7) | (unsigned)lane;
        }
        unsigned mk = mykey;
#pragma unroll
        for (int o = 16; o; o >>= 1) {
            unsigned ot = __shfl_xor_sync(FULL, mk, o);
            mk = mk < ot ? mk : ot;
        }
        if (lane < cap) {
            nb = myc;
            j = __float_as_int(myc.w);
            fm = 2.0f - qm;
        } else {
            nb = s_cand[warp][mk & 127u];
            j = (int)(mk >> 7);
            fm = 1.0f - qm;
        }
    } else {
        int m = cnt < NCAND ? cnt : NCAND;
        unsigned key;
        if (m <= 64) {
            unsigned v[2];
#pragma unroll
            for (int r = 0; r < 2; r++) {
                int idx = r * 32 + lane;
                v[r] = (idx < m)
                         ? (((unsigned)__float_as_int(s_cand[warp][idx].w) << 7) |
                            (unsigned)idx)
                         : 0xFFFFFFFFu;
            }
            bitonic_sort<2>(v, lane);
            key = v[0];
        } else {
            unsigned v[4];
#pragma unroll
            for (int r = 0; r < 4; r++) {
                int idx = r * 32 + lane;
                v[r] = (idx < m)
                         ? (((unsigned)__float_as_int(s_cand[warp][idx].w) << 7) |
                            (unsigned)idx)
                         : 0xFFFFFFFFu;
            }
            bitonic_sort<4>(v, lane);
            key = v[0];
        }
        nb = s_cand[warp][key & 127u];
        j = (int)(key >> 7);
        fm = 2.0f - qm;
    }

    s_ji[warp][lane] = j;
#pragma unroll
    for (int k = 0; k < NKP; k++) {
        float dx = nb.x - kp[3 * k];
        float dy = nb.y - kp[3 * k + 1];
        float dz = nb.z - kp[3 * k + 2];
        float d = sqrtf(dx * dx + dy * dy + dz * dz);
        float w = fmaxf(0.0f, 1.0f - d * INV_EXTENT) * fm;
        s_w2[warp][lane][k] = pack2(w, w);
    }
    __syncwarp();

    // ---- phase C: einsum over neighbors; weights via LDS.128 pairs ----
    int smax = (qm >= 1.0f) ? cap : NS;

    unsigned long long kwp[NKP];
#pragma unroll
    for (int k = 0; k < NKP; k++)
        kwp[k] = *(const unsigned long long*)(kw + k * CIN + 2 * lane);

    unsigned long long acc = 0ULL;
#pragma unroll 2
    for (int s2 = 0; s2 < smax; s2++) {
        int jj = s_ji[warp][s2];
        unsigned long long fch =
            *(const unsigned long long*)(g_featT + (size_t)(b * N2 + jj) * CIN + 2 * lane);
        const ulonglong2* wrow = (const ulonglong2*)&s_w2[warp][s2][0];
        unsigned long long cp = 0ULL;
#pragma unroll
        for (int i = 0; i < 7; i++) {
            ulonglong2 wv = wrow[i];
            cp = fma2(wv.x, kwp[2 * i], cp);
            cp = fma2(wv.y, kwp[2 * i + 1], cp);
        }
        cp = fma2(wrow[7].x, kwp[14], cp);
        acc = fma2(cp, fch, acc);
    }
    *(unsigned long long*)(g_tmp1 + (size_t)(b * N1 + q) * CIN + 2 * lane) = acc;
}

// ---------------------------------------------------------------------------
// k_gemm: 1x1 conv + BN stats. Block = 128 points x 128 outs, 256 threads,
//         thread = 8x8 register tile, channels staged in two 32-c chunks.
// ---------------------------------------------------------------------------
__global__ __launch_bounds__(256) void k_gemm(const float* __restrict__ Wout,
                                              float* __restrict__ out) {
    __shared__ float s_f[32][136];
    __shared__ float s_w[32][136];
    int p0 = blockIdx.x * 128;
    int t = threadIdx.x;
    int pg = t & 15;
    int og = t >> 4;

    float acc[8][8];
#pragma unroll
    for (int o = 0; o < 8; o++)
#pragma unroll
        for (int p = 0; p < 8; p++) acc[o][p] = 0.f;

#pragma unroll
    for (int ch = 0; ch < 2; ch++) {
        int c0 = ch * 32;
        __syncthreads();
        for (int e = t; e < 128 * 32; e += 256) {
            int p = e >> 5, c = e & 31;
            s_f[c][p] = g_tmp1[(size_t)(p0 + p) * CIN + c0 + c];
        }
        for (int e = t; e < COUT * 32; e += 256) {
            int o = e >> 5, c = e & 31;
            s_w[c][o] = Wout[o * CIN + c0 + c];
        }
        __syncthreads();

#pragma unroll 4
        for (int c = 0; c < 32; c++) {
            float4 f0 = *(const float4*)&s_f[c][pg * 8];
            float4 f1 = *(const float4*)&s_f[c][pg * 8 + 4];
            float4 w0 = *(const float4*)&s_w[c][og * 8];
            float4 w1 = *(const float4*)&s_w[c][og * 8 + 4];
            float fv[8] = {f0.x, f0.y, f0.z, f0.w, f1.x, f1.y, f1.z, f1.w};
            float wv[8] = {w0.x, w0.y, w0.z, w0.w, w1.x, w1.y, w1.z, w1.w};
#pragma unroll
            for (int o = 0; o < 8; o++)
#pragma unroll
                for (int p = 0; p < 8; p++) acc[o][p] += wv[o] * fv[p];
        }
    }

    int pglob = p0 + pg * 8;
    int b = pglob >> 11;
    int n = pglob & (N1 - 1);
#pragma unroll
    for (int o = 0; o < 8; o++) {
        int oc = og * 8 + o;
        *(float4*)&out[(size_t)(b * COUT + oc) * N1 + n] =
            make_float4(acc[o][0], acc[o][1], acc[o][2], acc[o][3]);
        *(float4*)&out[(size_t)(b * COUT + oc) * N1 + n + 4] =
            make_float4(acc[o][4], acc[o][5], acc[o][6], acc[o][7]);
        float sv = 0.f, sq = 0.f;
#pragma unroll
        for (int p = 0; p < 8; p++) {
            sv += acc[o][p];
            sq += acc[o][p] * acc[o][p];
        }
#pragma unroll
        for (int off = 8; off; off >>= 1) {
            sv += __shfl_xor_sync(0xffffffffu, sv, off);
            sq += __shfl_xor_sync(0xffffffffu, sq, off);
        }
        if (pg == 0) {
            atomicAdd(&g_sum[oc], sv);
            atomicAdd(&g_sumsq[oc], sq);
        }
    }
}

// ---------------------------------------------------------------------------
// k_bn: BatchNorm + ReLU, scale/bias once per block.
// ---------------------------------------------------------------------------
__global__ __launch_bounds__(256) void k_bn(float* __restrict__ out,
                                            const float* __restrict__ gamma,
                                            const float* __restrict__ beta) {
    __shared__ float s_sc, s_bi;
    int blk = blockIdx.x;
    int o = (blk >> 1) & (COUT - 1);
    if (threadIdx.x == 0) {
        const float invM = 1.0f / (float)(BB * N1);
        float m = g_sum[o] * invM;
        float var = g_sumsq[o] * invM - m * m;
        float sc = rsqrtf(var + 1e-5f) * gamma[o];
        s_sc = sc;
        s_bi = beta[o] - m * sc;
    }
    __syncthreads();
    float sc = s_sc, bi = s_bi;
    float4* o4 = (float4*)out;
    float4 v = o4[blk * 256 + threadIdx.x];
    v.x = fmaxf(v.x * sc + bi, 0.0f);
    v.y = fmaxf(v.y * sc + bi, 0.0f);
    v.z = fmaxf(v.z * sc + bi, 0.0f);
    v.w = fmaxf(v.w * sc + bi, 0.0f);
    o4[blk * 256 + threadIdx.x] = v;
}

// ---------------------------------------------------------------------------
extern "C" void kernel_launch(void* const* d_in, const int* in_sizes, int n_in,
                              void* d_out, int out_size) {
    const float* qxyz  = (const float*)d_in[0];
    const float* sxyz  = (const float*)d_in[1];
    const float* qmask = (const float*)d_in[2];
    const float* smask = (const float*)d_in[3];
    const float* feats = (const float*)d_in[4];
    const float* kp    = (const float*)d_in[5];
    const float* kw    = (const float*)d_in[6];
    const float* Wout  = (const float*)d_in[7];
    const float* gamma = (const float*)d_in[8];
    const float* beta  = (const float*)d_in[9];
    float* out = (float*)d_out;

    k_prep<<<BB * NBIN + BB * (CIN / 32) * (N2 / 256), 1024>>>(feats, sxyz, smask);
    k_group<<<dim3(N1 / 8, BB), 256>>>(qxyz, qmask, sxyz, kp, kw);
    k_gemm<<<(BB * N1) / 128, 256>>>(Wout, out);
    k_bn<<<(BB * COUT * N1) / 1024, 256>>>(out, gamma, beta);
}

// round 14
// speedup vs baseline: 1.1967x; 1.1967x over previous
#include <cuda_runtime.h>

#define BB 4
#define N1 2048
#define N2 8192
#define CIN 64
#define COUT 128
#define NKP 15
#define NS 32
#define RADIUS2 0.01f
#define INV_EXTENT 25.0f   /* 1 / 0.04 */
#define GRID 10
#define NCELL (GRID * GRID * GRID)
#define NCAND 128
#define NBIN 8             /* binning blocks per batch, 125 cells each */

// ---------------- scratch (__device__ globals: allocation-free rule) --------
__device__ __align__(16) float  g_featT[BB * N2 * CIN];  // 8 MB [B][N2][C]
__device__ __align__(16) float  g_tmp1[BB * N1 * CIN];   // 2 MB [B][N1][C]
__device__ float4 g_binned[BB * N2];             // points grouped by cell
__device__ int    g_cellStart[BB * (NCELL + 1)]; // cumulative starts per batch
__device__ float  g_sum[COUT];
__device__ float  g_sumsq[COUT];

// ---------------- f32x2 helpers (FFMA2) -------------------------------------
__device__ __forceinline__ unsigned long long pack2(float a, float b) {
    unsigned long long r;
    asm("mov.b64 %0, {%1, %2};" : "=l"(r) : "f"(a), "f"(b));
    return r;
}
__device__ __forceinline__ unsigned long long fma2(unsigned long long a,
                                                   unsigned long long b,
                                                   unsigned long long c) {
    unsigned long long d;
    asm("fma.rn.f32x2 %0, %1, %2, %3;" : "=l"(d) : "l"(a), "l"(b), "l"(c));
    return d;
}

__device__ __forceinline__ int cell1d(float x) {
    int c = (int)(x * (float)GRID);
    return c < 0 ? 0 : (c > GRID - 1 ? GRID - 1 : c);
}

// generic in-warp bitonic sort of R*32 keys (R regs/lane), ascending
template <int R>
__device__ __forceinline__ void bitonic_sort(unsigned (&v)[R], int lane) {
    const unsigned FULL = 0xffffffffu;
#pragma unroll
    for (int k = 2; k <= R * 32; k <<= 1) {
#pragma unroll
        for (int d = k >> 1; d > 0; d >>= 1) {
            if (d >= 32) {
                int rd = d >> 5;
#pragma unroll
                for (int r = 0; r < R; r++) {
                    if ((r & rd) == 0) {
                        int r2 = r + rd;
                        bool asc = (((r * 32) & k) == 0);
                        unsigned a = v[r], b2 = v[r2];
                        unsigned mn = a < b2 ? a : b2;
                        unsigned mx = a < b2 ? b2 : a;
                        v[r] = asc ? mn : mx;
                        v[r2] = asc ? mx : mn;
                    }
                }
            } else {
#pragma unroll
                for (int r = 0; r < R; r++) {
                    unsigned p = __shfl_xor_sync(FULL, v[r], d);
                    int idx = r * 32 + lane;
                    bool asc = ((idx & k) == 0);
                    bool lower = ((lane & d) == 0);
                    unsigned mn = v[r] < p ? v[r] : p;
                    unsigned mx = v[r] < p ? p : v[r];
                    v[r] = (lower == asc) ? mn : mx;
                }
            }
        }
    }
}

// ---------------------------------------------------------------------------
// k_prep: blocks 0..31  -> binning: block (b,k) owns cells [125k, 125k+125);
//                          points register-cached across both passes.
//         blocks 32..   -> transpose [B][C][N2] -> [B][N2][C]
// ---------------------------------------------------------------------------
__global__ __launch_bounds__(1024) void k_prep(const float* __restrict__ f,
                                               const float* __restrict__ sxyz,
                                               const float* __restrict__ smask) {
    __shared__ float tile[32][260];   // 33.3 KB transpose tile
    __shared__ int s_h[128];
    __shared__ int s_before[32];
    __shared__ int s_gbase;

    int t = threadIdx.x;
    int lane = t & 31, w = t >> 5;
    const unsigned FULL = 0xffffffffu;

    if (blockIdx.x < BB * NBIN) {
        // ================= binning block (b, k) =================
        int b = blockIdx.x >> 3, k = blockIdx.x & 7;
        int base = k * 125;

        if (b == 0 && k == 0 && t < COUT) { g_sum[t] = 0.0f; g_sumsq[t] = 0.0f; }
        if (t < 128) s_h[t] = 0;
        __syncthreads();

        // pass 1: load once, keep in registers; count-before + own-range hist
        float px[8], py[8], pz[8];
        int pc[8];
        int myBefore = 0;
#pragma unroll
        for (int i = 0; i < 8; i++) {
            int j = i * 1024 + t, p = b * N2 + j;
            float x = sxyz[p * 3], y = sxyz[p * 3 + 1], z = sxyz[p * 3 + 2];
            px[i] = x; py[i] = y; pz[i] = z;
            if (smask[p] > 0.0f) {
                int cid = (cell1d(x) * GRID + cell1d(y)) * GRID + cell1d(z);
                pc[i] = cid;
                if (cid < base) myBefore++;
                else if (cid < base + 125) atomicAdd(&s_h[cid - base], 1);
            } else {
                pc[i] = -1;
            }
        }
#pragma unroll
        for (int o = 16; o; o >>= 1) myBefore += __shfl_xor_sync(FULL, myBefore, o);
        if (lane == 0) s_before[w] = myBefore;
        __syncthreads();
        if (w == 0) {
            int sv = s_before[lane];
#pragma unroll
            for (int o = 16; o; o >>= 1) sv += __shfl_xor_sync(FULL, sv, o);
            if (lane == 0) s_gbase = sv;
        }
        __syncthreads();
        int gbase = s_gbase;
        __syncthreads();

        if (w == 0) {
            int c0 = base + 4 * lane;
            int v0 = (4 * lane + 0 < 125) ? s_h[4 * lane + 0] : 0;
            int v1 = (4 * lane + 1 < 125) ? s_h[4 * lane + 1] : 0;
            int v2 = (4 * lane + 2 < 125) ? s_h[4 * lane + 2] : 0;
            int v3 = (4 * lane + 3 < 125) ? s_h[4 * lane + 3] : 0;
            int sum = v0 + v1 + v2 + v3;
            int incl = sum;
#pragma unroll
            for (int o = 1; o < 32; o <<= 1) {
                int n = __shfl_up_sync(FULL, incl, o);
                if (lane >= o) incl += n;
            }
            int total = __shfl_sync(FULL, incl, 31);
            int e0 = incl - sum;
            int e1 = e0 + v0, e2 = e1 + v1, e3 = e2 + v2;
            int* gs = g_cellStart + b * (NCELL + 1);
            if (4 * lane + 0 < 125) { s_h[4 * lane + 0] = gbase + e0; gs[c0 + 0] = gbase + e0; }
            if (4 * lane + 1 < 125) { s_h[4 * lane + 1] = gbase + e1; gs[c0 + 1] = gbase + e1; }
            if (4 * lane + 2 < 125) { s_h[4 * lane + 2] = gbase + e2; gs[c0 + 2] = gbase + e2; }
            if (4 * lane + 3 < 125) { s_h[4 * lane + 3] = gbase + e3; gs[c0 + 3] = gbase + e3; }
            if (k == NBIN - 1 && lane == 0) gs[NCELL] = gbase + total;
        }
        __syncthreads();

        // pass 2: scatter own-range points straight from registers
#pragma unroll
        for (int i = 0; i < 8; i++) {
            int cid = pc[i];
            if (cid >= base && cid < base + 125) {
                int pos = atomicAdd(&s_h[cid - base], 1);
                g_binned[b * N2 + pos] =
                    make_float4(px[i], py[i], pz[i], __int_as_float(i * 1024 + t));
            }
        }
    } else {
        // ================= transpose tile: 32 channels x 256 points =========
        int tb = blockIdx.x - BB * NBIN;   // 0..255
        int n0 = (tb & 31) * 256;
        int c0 = ((tb >> 5) & 1) * 32;
        int b = tb >> 6;

        const float4* f4 = (const float4*)f;
#pragma unroll
        for (int i = 0; i < 2; i++) {
            int idx = t + i * 1024;
            int row = idx >> 6;
            int col4 = idx & 63;
            float4 vv = f4[(((size_t)(b * CIN + c0 + row) * N2) + n0) / 4 + col4];
            *(float4*)&tile[row][col4 * 4] = vv;
        }
        __syncthreads();
        float4* o4 = (float4*)g_featT;
#pragma unroll
        for (int i = 0; i < 2; i++) {
            int idx = t + i * 1024;
            int n = idx >> 3;
            int c4 = idx & 7;
            float4 vv = make_float4(tile[c4 * 4 + 0][n], tile[c4 * 4 + 1][n],
                                    tile[c4 * 4 + 2][n], tile[c4 * 4 + 3][n]);
            o4[((size_t)(b * N2 + n0 + n) * CIN + c0) / 4 + c4] = vv;
        }
    }
}

// ---------------------------------------------------------------------------
// k_group: grid-hashed ordered ball query + kernel-point weighting +
//          aggregation. One warp per query; 8 queries per 256-thread block.
//          (round-12 proven version — FROZEN)
// ---------------------------------------------------------------------------
__global__ __launch_bounds__(256) void k_group(
    const float* __restrict__ qxyz, const float* __restrict__ qmask,
    const float* __restrict__ sxyz,
    const float* __restrict__ kp, const float* __restrict__ kw) {
    __shared__ float4 s_cand[8][NCAND];                 // 16 KB
    __shared__ unsigned long long s_w2[8][NS][NKP];     // 30 KB {w,w} pairs
    __shared__ int s_ji[8][NS];                         // 1 KB

    int b = blockIdx.y;
    int warp = threadIdx.x >> 5, lane = threadIdx.x & 31;
    int q = blockIdx.x * 8 + warp;
    unsigned lmask = (1u << lane) - 1u;
    const unsigned FULL = 0xffffffffu;

    float qx = qxyz[(b * N1 + q) * 3 + 0];
    float qy = qxyz[(b * N1 + q) * 3 + 1];
    float qz = qxyz[(b * N1 + q) * 3 + 2];
    float qm = qmask[b * N1 + q];

    // ---- phase A: flattened candidate scan over 9 z-contiguous segments ----
    int cx = cell1d(qx), cy = cell1d(qy), cz = cell1d(qz);
    int z0 = cz > 0 ? cz - 1 : 0, z1 = cz < GRID - 1 ? cz + 1 : GRID - 1;

    const int* cs = g_cellStart + b * (NCELL + 1);
    int seg_s0 = 0, seg_len = 0;
    if (lane < 9) {
        int ix = cx + lane / 3 - 1;
        int iy = cy + lane % 3 - 1;
        if (ix >= 0 && ix < GRID && iy >= 0 && iy < GRID) {
            int cbase = (ix * GRID + iy) * GRID;
            seg_s0 = cs[cbase + z0];
            seg_len = cs[cbase + z1 + 1] - seg_s0;
        }
    }
    int cum = seg_len;
#pragma unroll
    for (int o = 1; o < 16; o <<= 1) {
        int n = __shfl_up_sync(FULL, cum, o);
        if (lane >= o) cum += n;
    }
    int T = __shfl_sync(FULL, cum, 8);
    int cumk[9], s0k[9];
#pragma unroll
    for (int k = 0; k < 9; k++) {
        cumk[k] = __shfl_sync(FULL, cum, k);
        s0k[k] = __shfl_sync(FULL, seg_s0, k);
    }

    int cnt = 0;
    for (int t0 = 0; t0 < T; t0 += 32) {
        int g = t0 + lane;
        bool inb = g < T;
        int addr = s0k[0] + g;
#pragma unroll
        for (int k = 1; k < 9; k++)
            if (g >= cumk[k - 1]) addr = s0k[k] + (g - cumk[k - 1]);
        if (!inb) addr = 0;
        float4 p = g_binned[b * N2 + addr];
        float rx = p.x - qx, ry = p.y - qy, rz = p.z - qz;
        float d2 = rx * rx + ry * ry + rz * rz;
        bool valid = inb && (d2 < RADIUS2);
        unsigned bal = __ballot_sync(FULL, valid);
        int slot = cnt + __popc(bal & lmask);
        if (valid && slot < NCAND)
            s_cand[warp][slot] = make_float4(rx, ry, rz, p.w);
        cnt += __popc(bal);
    }
    __syncwarp();

    // ---- phase B: first-32 SET selection + kernel-point weights ----
    int cap = cnt < NS ? cnt : NS;
    float4 nb;
    int j;
    float fm;

    if (cnt == 0) {
        nb = make_float4(sxyz[b * N2 * 3] - qx, sxyz[b * N2 * 3 + 1] - qy,
                         sxyz[b * N2 * 3 + 2] - qz, 0.0f);
        j = 0;
        fm = 1.0f - qm;
    } else if (cnt <= NS) {
        unsigned mykey = 0xFFFFFFFFu;
        float4 myc;
        if (lane < cap) {
            myc = s_cand[warp][lane];
            mykey = ((unsigned)__float_as_int(myc.w) << 7) | (unsigned)lane;
        }
        unsigned mk = mykey;
#pragma unroll
        for (int o = 16; o; o >>= 1) {
            unsigned ot = __shfl_xor_sync(FULL, mk, o);
            mk = mk < ot ? mk : ot;
        }
        if (lane < cap) {
            nb = myc;
            j = __float_as_int(myc.w);
            fm = 2.0f - qm;
        } else {
            nb = s_cand[warp][mk & 127u];
            j = (int)(mk >> 7);
            fm = 1.0f - qm;
        }
    } else {
        int m = cnt < NCAND ? cnt : NCAND;
        unsigned key;
        if (m <= 64) {
            unsigned v[2];
#pragma unroll
            for (int r = 0; r < 2; r++) {
                int idx = r * 32 + lane;
                v[r] = (idx < m)
                         ? (((unsigned)__float_as_int(s_cand[warp][idx].w) << 7) |
                            (unsigned)idx)
                         : 0xFFFFFFFFu;
            }
            bitonic_sort<2>(v, lane);
            key = v[0];
        } else {
            unsigned v[4];
#pragma unroll
            for (int r = 0; r < 4; r++) {
                int idx = r * 32 + lane;
                v[r] = (idx < m)
                         ? (((unsigned)__float_as_int(s_cand[warp][idx].w) << 7) |
                            (unsigned)idx)
                         : 0xFFFFFFFFu;
            }
            bitonic_sort<4>(v, lane);
            key = v[0];
        }
        nb = s_cand[warp][key & 127u];
        j = (int)(key >> 7);
        fm = 2.0f - qm;
    }

    s_ji[warp][lane] = j;
#pragma unroll
    for (int k = 0; k < NKP; k++) {
        float dx = nb.x - kp[3 * k];
        float dy = nb.y - kp[3 * k + 1];
        float dz = nb.z - kp[3 * k + 2];
        float d = sqrtf(dx * dx + dy * dy + dz * dz);
        float w = fmaxf(0.0f, 1.0f - d * INV_EXTENT) * fm;
        s_w2[warp][lane][k] = pack2(w, w);
    }
    __syncwarp();

    // ---- phase C: einsum over neighbors, FFMA2 on channel pairs ----
    int smax = (qm >= 1.0f) ? cap : NS;

    unsigned long long kwp[NKP];
#pragma unroll
    for (int k = 0; k < NKP; k++)
        kwp[k] = *(const unsigned long long*)(kw + k * CIN + 2 * lane);

    unsigned long long acc = 0ULL;
#pragma unroll 4
    for (int s2 = 0; s2 < smax; s2++) {
        int jj = s_ji[warp][s2];
        unsigned long long fch =
            *(const unsigned long long*)(g_featT + (size_t)(b * N2 + jj) * CIN + 2 * lane);
        unsigned long long cp = 0ULL;
#pragma unroll
        for (int k = 0; k < NKP; k++)
            cp = fma2(s_w2[warp][s2][k], kwp[k], cp);
        acc = fma2(cp, fch, acc);
    }
    *(unsigned long long*)(g_tmp1 + (size_t)(b * N1 + q) * CIN + 2 * lane) = acc;
}

// ---------------------------------------------------------------------------
// k_gemm: 1x1 conv + BN stats. Block = 128 points x 128 outs, 256 threads,
//         thread = 8x8 register tile, channels staged in two 32-c chunks.
//         (round-12 proven version — FROZEN)
// ---------------------------------------------------------------------------
__global__ __launch_bounds__(256) void k_gemm(const float* __restrict__ Wout,
                                              float* __restrict__ out) {
    __shared__ float s_f[32][136];
    __shared__ float s_w[32][136];
    int p0 = blockIdx.x * 128;
    int t = threadIdx.x;
    int pg = t & 15;
    int og = t >> 4;

    float acc[8][8];
#pragma unroll
    for (int o = 0; o < 8; o++)
#pragma unroll
        for (int p = 0; p < 8; p++) acc[o][p] = 0.f;

#pragma unroll
    for (int ch = 0; ch < 2; ch++) {
        int c0 = ch * 32;
        __syncthreads();
        for (int e = t; e < 128 * 32; e += 256) {
            int p = e >> 5, c = e & 31;
            s_f[c][p] = g_tmp1[(size_t)(p0 + p) * CIN + c0 + c];
        }
        for (int e = t; e < COUT * 32; e += 256) {
            int o = e >> 5, c = e & 31;
            s_w[c][o] = Wout[o * CIN + c0 + c];
        }
        __syncthreads();

#pragma unroll 4
        for (int c = 0; c < 32; c++) {
            float4 f0 = *(const float4*)&s_f[c][pg * 8];
            float4 f1 = *(const float4*)&s_f[c][pg * 8 + 4];
            float4 w0 = *(const float4*)&s_w[c][og * 8];
            float4 w1 = *(const float4*)&s_w[c][og * 8 + 4];
            float fv[8] = {f0.x, f0.y, f0.z, f0.w, f1.x, f1.y, f1.z, f1.w};
            float wv[8] = {w0.x, w0.y, w0.z, w0.w, w1.x, w1.y, w1.z, w1.w};
#pragma unroll
            for (int o = 0; o < 8; o++)
#pragma unroll
                for (int p = 0; p < 8; p++) acc[o][p] += wv[o] * fv[p];
        }
    }

    int pglob = p0 + pg * 8;
    int b = pglob >> 11;
    int n = pglob & (N1 - 1);
#pragma unroll
    for (int o = 0; o < 8; o++) {
        int oc = og * 8 + o;
        *(float4*)&out[(size_t)(b * COUT + oc) * N1 + n] =
            make_float4(acc[o][0], acc[o][1], acc[o][2], acc[o][3]);
        *(float4*)&out[(size_t)(b * COUT + oc) * N1 + n + 4] =
            make_float4(acc[o][4], acc[o][5], acc[o][6], acc[o][7]);
        float sv = 0.f, sq = 0.f;
#pragma unroll
        for (int p = 0; p < 8; p++) {
            sv += acc[o][p];
            sq += acc[o][p] * acc[o][p];
        }
#pragma unroll
        for (int off = 8; off; off >>= 1) {
            sv += __shfl_xor_sync(0xffffffffu, sv, off);
            sq += __shfl_xor_sync(0xffffffffu, sq, off);
        }
        if (pg == 0) {
            atomicAdd(&g_sum[oc], sv);
            atomicAdd(&g_sumsq[oc], sq);
        }
    }
}

// ---------------------------------------------------------------------------
// k_bn: BatchNorm + ReLU, scale/bias once per block. (FROZEN)
// ---------------------------------------------------------------------------
__global__ __launch_bounds__(256) void k_bn(float* __restrict__ out,
                                            const float* __restrict__ gamma,
                                            const float* __restrict__ beta) {
    __shared__ float s_sc, s_bi;
    int blk = blockIdx.x;
    int o = (blk >> 1) & (COUT - 1);
    if (threadIdx.x == 0) {
        const float invM = 1.0f / (float)(BB * N1);
        float m = g_sum[o] * invM;
        float var = g_sumsq[o] * invM - m * m;
        float sc = rsqrtf(var + 1e-5f) * gamma[o];
        s_sc = sc;
        s_bi = beta[o] - m * sc;
    }
    __syncthreads();
    float sc = s_sc, bi = s_bi;
    float4* o4 = (float4*)out;
    float4 v = o4[blk * 256 + threadIdx.x];
    v.x = fmaxf(v.x * sc + bi, 0.0f);
    v.y = fmaxf(v.y * sc + bi, 0.0f);
    v.z = fmaxf(v.z * sc + bi, 0.0f);
    v.w = fmaxf(v.w * sc + bi, 0.0f);
    o4[blk * 256 + threadIdx.x] = v;
}

// ---------------------------------------------------------------------------
extern "C" void kernel_launch(void* const* d_in, const int* in_sizes, int n_in,
                              void* d_out, int out_size) {
    const float* qxyz  = (const float*)d_in[0];
    const float* sxyz  = (const float*)d_in[1];
    const float* qmask = (const float*)d_in[2];
    const float* smask = (const float*)d_in[3];
    const float* feats = (const float*)d_in[4];
    const float* kp    = (const float*)d_in[5];
    const float* kw    = (const float*)d_in[6];
    const float* Wout  = (const float*)d_in[7];
    const float* gamma = (const float*)d_in[8];
    const float* beta  = (const float*)d_in[9];
    float* out = (float*)d_out;

    k_prep<<<BB * NBIN + BB * (CIN / 32) * (N2 / 256), 1024>>>(feats, sxyz, smask);
    k_group<<<dim3(N1 / 8, BB), 256>>>(qxyz, qmask, sxyz, kp, kw);
    k_gemm<<<(BB * N1) / 128, 256>>>(Wout, out);
    k_bn<<<(BB * COUT * N1) / 1024, 256>>>(out, gamma, beta);
}